// round 6
// baseline (speedup 1.0000x reference)
#include <cuda_runtime.h>
#include <cuda_bf16.h>
#include <math.h>

#define NROWS 256
#define DLEN  196608              // 3*256*256
#define CHUNKS 4
#define TPB   512
#define NBLK  (NROWS * CHUNKS)
#define F4_PER_CHUNK (DLEN / 4 / CHUNKS)   // 12288 -> 24 float4 per thread

// scratch: per (row,chunk) partials [Sz, Sb, Szz, Sbb, Szb]
__device__ float g_part[NBLK][5];
__device__ unsigned int g_done = 0;        // reset by the finalizing block each launch

__global__ __launch_bounds__(TPB)
void pixcorr_fused(const float* __restrict__ preds, const float* __restrict__ targ,
                   float* __restrict__ out) {
    const int blk   = blockIdx.x;         // 0..1023
    const int row   = blk >> 2;
    const int chunk = blk & 3;

    const float4* __restrict__ z4 =
        reinterpret_cast<const float4*>(targ) + (size_t)row * (DLEN / 4) + (size_t)chunk * F4_PER_CHUNK;
    const float4* __restrict__ b4 =
        reinterpret_cast<const float4*>(preds) + (size_t)row * (DLEN / 4) + (size_t)chunk * F4_PER_CHUNK;

    float sz = 0.f, sb = 0.f, szz = 0.f, sbb = 0.f, szb = 0.f;

    #pragma unroll 4
    for (int i = threadIdx.x; i < F4_PER_CHUNK; i += TPB) {
        float4 zv = __ldcs(&z4[i]);        // read-once stream: evict-first
        float4 bv = __ldcs(&b4[i]);
        sz  += (zv.x + zv.y) + (zv.z + zv.w);
        sb  += (bv.x + bv.y) + (bv.z + bv.w);
        szz  = fmaf(zv.x, zv.x, fmaf(zv.y, zv.y, fmaf(zv.z, zv.z, fmaf(zv.w, zv.w, szz))));
        sbb  = fmaf(bv.x, bv.x, fmaf(bv.y, bv.y, fmaf(bv.z, bv.z, fmaf(bv.w, bv.w, sbb))));
        szb  = fmaf(zv.x, bv.x, fmaf(zv.y, bv.y, fmaf(zv.z, bv.z, fmaf(zv.w, bv.w, szb))));
    }

    // intra-warp butterfly reduction (5 values)
    #pragma unroll
    for (int o = 16; o > 0; o >>= 1) {
        sz  += __shfl_xor_sync(0xFFFFFFFFu, sz,  o);
        sb  += __shfl_xor_sync(0xFFFFFFFFu, sb,  o);
        szz += __shfl_xor_sync(0xFFFFFFFFu, szz, o);
        sbb += __shfl_xor_sync(0xFFFFFFFFu, sbb, o);
        szb += __shfl_xor_sync(0xFFFFFFFFu, szb, o);
    }

    __shared__ float sm[5][TPB / 32];    // 16 warps
    const int w = threadIdx.x >> 5;
    const int l = threadIdx.x & 31;
    if (l == 0) {
        sm[0][w] = sz; sm[1][w] = sb; sm[2][w] = szz; sm[3][w] = sbb; sm[4][w] = szb;
    }
    __syncthreads();

    if (threadIdx.x < 5) {
        float a = 0.f;
        #pragma unroll
        for (int i = 0; i < TPB / 32; i++) a += sm[threadIdx.x][i];
        g_part[blk][threadIdx.x] = a;
    }

    // ---- last-block finalization (threadFenceReduction pattern) ----
    __shared__ bool is_last;
    __syncthreads();                       // partial stores done block-wide
    if (threadIdx.x == 0) {
        __threadfence();                   // publish this block's partials
        unsigned int old = atomicAdd(&g_done, 1u);
        is_last = (old == (unsigned int)(NBLK - 1));
    }
    __syncthreads();
    if (!is_last) return;

    __threadfence();                       // acquire: see all blocks' partials

    const int r = threadIdx.x;             // threads 0..255 handle one row each
    __shared__ double smem[NROWS];
    if (r < NROWS) {
        double dsz = 0.0, dsb = 0.0, dszz = 0.0, dsbb = 0.0, dszb = 0.0;
        #pragma unroll
        for (int c = 0; c < CHUNKS; c++) {
            const float* p = g_part[r * CHUNKS + c];
            dsz  += (double)p[0];
            dsb  += (double)p[1];
            dszz += (double)p[2];
            dsbb += (double)p[3];
            dszb += (double)p[4];
        }
        const double Dd = (double)DLEN;
        const double num = dszb - dsz * dsb / Dd;
        const double vz  = dszz - dsz * dsz / Dd;
        const double vb  = dsbb - dsb * dsb / Dd;
        smem[r] = num / (sqrt(vz) * sqrt(vb) + 1e-6);
    }
    __syncthreads();

    // fixed-order pairwise tree over 256 rows: deterministic across replays
    #pragma unroll
    for (int s = NROWS / 2; s > 0; s >>= 1) {
        if (r < s) smem[r] += smem[r + s];
        __syncthreads();
    }
    if (r == 0) {
        out[0] = (float)(smem[0] / (double)NROWS);
        g_done = 0;                        // reset for next graph replay
    }
}

extern "C" void kernel_launch(void* const* d_in, const int* in_sizes, int n_in,
                              void* d_out, int out_size) {
    const float* preds = (const float*)d_in[0];
    const float* targ  = (const float*)d_in[1];
    float* out = (float*)d_out;

    pixcorr_fused<<<NBLK, TPB>>>(preds, targ, out);
}

// round 8
// speedup vs baseline: 1.1500x; 1.1500x over previous
#include <cuda_runtime.h>
#include <cuda_bf16.h>
#include <math.h>

#define NROWS 256
#define DLEN  196608              // 3*256*256
#define CHUNKS 4
#define TPB   512
#define NBLK  (NROWS * CHUNKS)
#define F4_PER_CHUNK (DLEN / 4 / CHUNKS)   // 12288 -> 24 float4 per thread

// scratch: per (row,chunk) partials [Sz, Sb, Szz, Sbb, Szb]
__device__ float g_part[NBLK][5];
__device__ unsigned int g_done = 0;        // reset by the finalizing block each launch

__global__ __launch_bounds__(TPB, 4)       // cap at 32 regs -> 4 blocks/SM, 100% occ
void pixcorr_fused(const float* __restrict__ preds, const float* __restrict__ targ,
                   float* __restrict__ out) {
    const int blk   = blockIdx.x;         // 0..1023
    const int row   = blk >> 2;
    const int chunk = blk & 3;

    const float4* __restrict__ z4 =
        reinterpret_cast<const float4*>(targ) + (size_t)row * (DLEN / 4) + (size_t)chunk * F4_PER_CHUNK;
    const float4* __restrict__ b4 =
        reinterpret_cast<const float4*>(preds) + (size_t)row * (DLEN / 4) + (size_t)chunk * F4_PER_CHUNK;

    float sz = 0.f, sb = 0.f, szz = 0.f, sbb = 0.f, szb = 0.f;

    #pragma unroll 4
    for (int i = threadIdx.x; i < F4_PER_CHUNK; i += TPB) {
        float4 zv = z4[i];                 // plain LDG.128 (no cache-policy hint)
        float4 bv = b4[i];
        sz  += (zv.x + zv.y) + (zv.z + zv.w);
        sb  += (bv.x + bv.y) + (bv.z + bv.w);
        szz  = fmaf(zv.x, zv.x, fmaf(zv.y, zv.y, fmaf(zv.z, zv.z, fmaf(zv.w, zv.w, szz))));
        sbb  = fmaf(bv.x, bv.x, fmaf(bv.y, bv.y, fmaf(bv.z, bv.z, fmaf(bv.w, bv.w, sbb))));
        szb  = fmaf(zv.x, bv.x, fmaf(zv.y, bv.y, fmaf(zv.z, bv.z, fmaf(zv.w, bv.w, szb))));
    }

    // intra-warp butterfly reduction (5 values)
    #pragma unroll
    for (int o = 16; o > 0; o >>= 1) {
        sz  += __shfl_xor_sync(0xFFFFFFFFu, sz,  o);
        sb  += __shfl_xor_sync(0xFFFFFFFFu, sb,  o);
        szz += __shfl_xor_sync(0xFFFFFFFFu, szz, o);
        sbb += __shfl_xor_sync(0xFFFFFFFFu, sbb, o);
        szb += __shfl_xor_sync(0xFFFFFFFFu, szb, o);
    }

    __shared__ float sm[5][TPB / 32];    // 16 warps
    const int w = threadIdx.x >> 5;
    const int l = threadIdx.x & 31;
    if (l == 0) {
        sm[0][w] = sz; sm[1][w] = sb; sm[2][w] = szz; sm[3][w] = sbb; sm[4][w] = szb;
    }
    __syncthreads();

    if (threadIdx.x < 5) {
        float a = 0.f;
        #pragma unroll
        for (int i = 0; i < TPB / 32; i++) a += sm[threadIdx.x][i];
        g_part[blk][threadIdx.x] = a;
    }

    // ---- last-block finalization (threadFenceReduction pattern) ----
    __shared__ bool is_last;
    __syncthreads();                       // partial stores done block-wide
    if (threadIdx.x == 0) {
        __threadfence();                   // publish this block's partials
        unsigned int old = atomicAdd(&g_done, 1u);
        is_last = (old == (unsigned int)(NBLK - 1));
    }
    __syncthreads();
    if (!is_last) return;

    __threadfence();                       // acquire: see all blocks' partials

    const int r = threadIdx.x;             // threads 0..255 handle one row each
    __shared__ double smem[NROWS];
    if (r < NROWS) {
        double dsz = 0.0, dsb = 0.0, dszz = 0.0, dsbb = 0.0, dszb = 0.0;
        #pragma unroll
        for (int c = 0; c < CHUNKS; c++) {
            const float* p = g_part[r * CHUNKS + c];
            dsz  += (double)p[0];
            dsb  += (double)p[1];
            dszz += (double)p[2];
            dsbb += (double)p[3];
            dszb += (double)p[4];
        }
        const double Dd = (double)DLEN;
        const double num = dszb - dsz * dsb / Dd;
        const double vz  = dszz - dsz * dsz / Dd;
        const double vb  = dsbb - dsb * dsb / Dd;
        smem[r] = num / (sqrt(vz) * sqrt(vb) + 1e-6);
    }
    __syncthreads();

    // fixed-order pairwise tree over 256 rows: deterministic across replays
    #pragma unroll
    for (int s = NROWS / 2; s > 0; s >>= 1) {
        if (r < s) smem[r] += smem[r + s];
        __syncthreads();
    }
    if (r == 0) {
        out[0] = (float)(smem[0] / (double)NROWS);
        g_done = 0;                        // reset for next graph replay
    }
}

extern "C" void kernel_launch(void* const* d_in, const int* in_sizes, int n_in,
                              void* d_out, int out_size) {
    const float* preds = (const float*)d_in[0];
    const float* targ  = (const float*)d_in[1];
    float* out = (float*)d_out;

    pixcorr_fused<<<NBLK, TPB>>>(preds, targ, out);
}

// round 9
// speedup vs baseline: 1.1692x; 1.0167x over previous
#include <cuda_runtime.h>
#include <cuda_bf16.h>
#include <math.h>

#define NROWS 256
#define DLEN  196608              // 3*256*256
#define CHUNKS 4
#define TPB   512
#define NBLK  (NROWS * CHUNKS)
#define F4_PER_CHUNK (DLEN / 4 / CHUNKS)   // 12288 -> 24 float4 per thread

// scratch: per (row,chunk) partials [Sz, Sb, Szz, Sbb, Szb]
__device__ float g_part[NBLK][5];
__device__ unsigned int g_done = 0;        // reset by the finalizing block each launch

__global__ __launch_bounds__(TPB)          // NO min-blocks cap: let regs float for max MLP
void pixcorr_fused(const float* __restrict__ preds, const float* __restrict__ targ,
                   float* __restrict__ out) {
    const int blk   = blockIdx.x;         // 0..1023
    const int row   = blk >> 2;
    const int chunk = blk & 3;

    const float4* __restrict__ z4 =
        reinterpret_cast<const float4*>(targ) + (size_t)row * (DLEN / 4) + (size_t)chunk * F4_PER_CHUNK;
    const float4* __restrict__ b4 =
        reinterpret_cast<const float4*>(preds) + (size_t)row * (DLEN / 4) + (size_t)chunk * F4_PER_CHUNK;

    float sz = 0.f, sb = 0.f, szz = 0.f, sbb = 0.f, szb = 0.f;

    #pragma unroll 4
    for (int i = threadIdx.x; i < F4_PER_CHUNK; i += TPB) {
        float4 zv = z4[i];                 // plain LDG.128
        float4 bv = b4[i];
        sz  += (zv.x + zv.y) + (zv.z + zv.w);
        sb  += (bv.x + bv.y) + (bv.z + bv.w);
        szz  = fmaf(zv.x, zv.x, fmaf(zv.y, zv.y, fmaf(zv.z, zv.z, fmaf(zv.w, zv.w, szz))));
        sbb  = fmaf(bv.x, bv.x, fmaf(bv.y, bv.y, fmaf(bv.z, bv.z, fmaf(bv.w, bv.w, sbb))));
        szb  = fmaf(zv.x, bv.x, fmaf(zv.y, bv.y, fmaf(zv.z, bv.z, fmaf(zv.w, bv.w, szb))));
    }

    // intra-warp butterfly reduction (5 values)
    #pragma unroll
    for (int o = 16; o > 0; o >>= 1) {
        sz  += __shfl_xor_sync(0xFFFFFFFFu, sz,  o);
        sb  += __shfl_xor_sync(0xFFFFFFFFu, sb,  o);
        szz += __shfl_xor_sync(0xFFFFFFFFu, szz, o);
        sbb += __shfl_xor_sync(0xFFFFFFFFu, sbb, o);
        szb += __shfl_xor_sync(0xFFFFFFFFu, szb, o);
    }

    __shared__ float sm[5][TPB / 32];    // 16 warps
    const int w = threadIdx.x >> 5;
    const int l = threadIdx.x & 31;
    if (l == 0) {
        sm[0][w] = sz; sm[1][w] = sb; sm[2][w] = szz; sm[3][w] = sbb; sm[4][w] = szb;
    }
    __syncthreads();

    if (threadIdx.x < 5) {
        float a = 0.f;
        #pragma unroll
        for (int i = 0; i < TPB / 32; i++) a += sm[threadIdx.x][i];
        g_part[blk][threadIdx.x] = a;
    }

    // ---- last-block finalization (threadFenceReduction pattern) ----
    __shared__ bool is_last;
    __syncthreads();                       // partial stores done block-wide
    if (threadIdx.x == 0) {
        __threadfence();                   // publish this block's partials
        unsigned int old = atomicAdd(&g_done, 1u);
        is_last = (old == (unsigned int)(NBLK - 1));
    }
    __syncthreads();
    if (!is_last) return;

    __threadfence();                       // acquire: see all blocks' partials

    const int r = threadIdx.x;             // threads 0..255 handle one row each
    __shared__ double smem[NROWS];
    if (r < NROWS) {
        double dsz = 0.0, dsb = 0.0, dszz = 0.0, dsbb = 0.0, dszb = 0.0;
        #pragma unroll
        for (int c = 0; c < CHUNKS; c++) {
            const float* p = g_part[r * CHUNKS + c];
            dsz  += (double)p[0];
            dsb  += (double)p[1];
            dszz += (double)p[2];
            dsbb += (double)p[3];
            dszb += (double)p[4];
        }
        const double Dd = (double)DLEN;
        const double num = dszb - dsz * dsb / Dd;
        const double vz  = dszz - dsz * dsz / Dd;
        const double vb  = dsbb - dsb * dsb / Dd;
        smem[r] = num / (sqrt(vz) * sqrt(vb) + 1e-6);
    }
    __syncthreads();

    // fixed-order pairwise tree over 256 rows: deterministic across replays
    #pragma unroll
    for (int s = NROWS / 2; s > 0; s >>= 1) {
        if (r < s) smem[r] += smem[r + s];
        __syncthreads();
    }
    if (r == 0) {
        out[0] = (float)(smem[0] / (double)NROWS);
        g_done = 0;                        // reset for next graph replay
    }
}

extern "C" void kernel_launch(void* const* d_in, const int* in_sizes, int n_in,
                              void* d_out, int out_size) {
    const float* preds = (const float*)d_in[0];
    const float* targ  = (const float*)d_in[1];
    float* out = (float*)d_out;

    pixcorr_fused<<<NBLK, TPB>>>(preds, targ, out);
}